// round 1
// baseline (speedup 1.0000x reference)
#include <cuda_runtime.h>
#include <cstdint>

// Problem dims (fixed)
#define Bd 8
#define Sd 2048
#define Id 1024
#define Hd 4096
#define Od 1024
#define M_TOT (Bd * Sd)          // 16384

// Recurrence chunking
#define NCHUNK 16
#define CHUNK  128               // NCHUNK*CHUNK == Sd
#define NCH    (Bd * Id)         // 8192 channels

// Scratch (allocation-free: __device__ globals)
__device__ float g_decay[(size_t)M_TOT * Id];     // 64 MB
__device__ float g_combined[(size_t)M_TOT * Id];  // 64 MB
__device__ float g_hidden[(size_t)M_TOT * Hd];    // 256 MB
__device__ float g_P[NCHUNK * NCH];
__device__ float g_Q[NCHUNK * NCH];

// ---------------------------------------------------------------------------
// TF32 helpers
// ---------------------------------------------------------------------------
__device__ __forceinline__ uint32_t f2tf(float x) {
    uint32_t u;
    asm("cvt.rna.tf32.f32 %0, %1;" : "=r"(u) : "f"(x));
    return u;
}

__device__ __forceinline__ void store_cvt(float* dst, float4 v) {
    uint4 u;
    u.x = f2tf(v.x); u.y = f2tf(v.y); u.z = f2tf(v.z); u.w = f2tf(v.w);
    *reinterpret_cast<uint4*>(dst) = u;
}

__device__ __forceinline__ void mma8(float c[4], const uint32_t a[4], const uint32_t b[2]) {
    asm volatile(
        "mma.sync.aligned.m16n8k8.row.col.f32.tf32.tf32.f32 "
        "{%0,%1,%2,%3}, {%4,%5,%6,%7}, {%8,%9}, {%0,%1,%2,%3};"
        : "+f"(c[0]), "+f"(c[1]), "+f"(c[2]), "+f"(c[3])
        : "r"(a[0]), "r"(a[1]), "r"(a[2]), "r"(a[3]), "r"(b[0]), "r"(b[1]));
}

template <int EPI>
__device__ __forceinline__ float epi_act(float v) {
    if (EPI == 1) return v > 0.f ? v : 0.f;            // relu
    if (EPI == 2) return 1.f / (1.f + __expf(-v));     // sigmoid
    return v;
}

// ---------------------------------------------------------------------------
// GEMM: C[M,N] = act(A[M,K] @ B[N,K]^T + bias[N])
// Both operands K-contiguous (row-major). Block 128x128, 8 warps (2x4),
// warp tile 64x32, TF32 m16n8k8 mma. Double-buffered smem, stride-20 rows
// (conflict-free for the fragment gather pattern).
// ---------------------------------------------------------------------------
#define SLD 20  // smem row stride in floats (16 data + 4 pad)

template <int EPI>
__global__ void __launch_bounds__(256, 2)
gemm_tn(const float* __restrict__ A, const float* __restrict__ Bm,
        const float* __restrict__ bias, float* __restrict__ C,
        int M, int N, int K) {
    __shared__ float As[2][128 * SLD];
    __shared__ float Bs[2][128 * SLD];

    const int tid  = threadIdx.x;
    const int lane = tid & 31;
    const int warp = tid >> 5;
    const int g    = lane >> 2;      // group id 0..7
    const int tig  = lane & 3;       // thread-in-group 0..3
    const int wm   = (warp >> 2) * 64;   // warp M offset in block tile
    const int wn   = (warp & 3) * 32;    // warp N offset
    const int ldrow = tid >> 2;          // 0..63
    const int ldcol = (tid & 3) << 2;    // 0,4,8,12

    const size_t blockM = (size_t)blockIdx.y * 128;
    const size_t blockN = (size_t)blockIdx.x * 128;

    const float* Ag0 = A  + (blockM + ldrow) * (size_t)K + ldcol;
    const float* Ag1 = Ag0 + (size_t)64 * K;
    const float* Bg0 = Bm + (blockN + ldrow) * (size_t)K + ldcol;
    const float* Bg1 = Bg0 + (size_t)64 * K;

    float c[4][4][4] = {};

    // prologue: tile 0 -> smem buf 0
    {
        float4 a0 = *(const float4*)Ag0;
        float4 a1 = *(const float4*)Ag1;
        float4 b0 = *(const float4*)Bg0;
        float4 b1 = *(const float4*)Bg1;
        store_cvt(&As[0][ldrow * SLD + ldcol], a0);
        store_cvt(&As[0][(ldrow + 64) * SLD + ldcol], a1);
        store_cvt(&Bs[0][ldrow * SLD + ldcol], b0);
        store_cvt(&Bs[0][(ldrow + 64) * SLD + ldcol], b1);
    }
    __syncthreads();

    const int nk = K >> 4;
    for (int kt = 0; kt < nk; kt++) {
        const int buf = kt & 1;
        float4 a0, a1, b0, b1;
        const bool has_next = (kt + 1 < nk);
        if (has_next) {
            const int k0 = (kt + 1) << 4;
            a0 = *(const float4*)(Ag0 + k0);
            a1 = *(const float4*)(Ag1 + k0);
            b0 = *(const float4*)(Bg0 + k0);
            b1 = *(const float4*)(Bg1 + k0);
        }

#pragma unroll
        for (int kk = 0; kk < 16; kk += 8) {
            uint32_t af[4][4];
            uint32_t bf[4][2];
#pragma unroll
            for (int mt = 0; mt < 4; mt++) {
                const float* p = &As[buf][(wm + mt * 16 + g) * SLD + kk + tig];
                af[mt][0] = __float_as_uint(p[0]);
                af[mt][1] = __float_as_uint(p[8 * SLD]);
                af[mt][2] = __float_as_uint(p[4]);
                af[mt][3] = __float_as_uint(p[8 * SLD + 4]);
            }
#pragma unroll
            for (int nt = 0; nt < 4; nt++) {
                const float* p = &Bs[buf][(wn + nt * 8 + g) * SLD + kk + tig];
                bf[nt][0] = __float_as_uint(p[0]);
                bf[nt][1] = __float_as_uint(p[4]);
            }
#pragma unroll
            for (int mt = 0; mt < 4; mt++)
#pragma unroll
                for (int nt = 0; nt < 4; nt++)
                    mma8(c[mt][nt], af[mt], bf[nt]);
        }

        if (has_next) {
            store_cvt(&As[buf ^ 1][ldrow * SLD + ldcol], a0);
            store_cvt(&As[buf ^ 1][(ldrow + 64) * SLD + ldcol], a1);
            store_cvt(&Bs[buf ^ 1][ldrow * SLD + ldcol], b0);
            store_cvt(&Bs[buf ^ 1][(ldrow + 64) * SLD + ldcol], b1);
        }
        __syncthreads();
    }

    // epilogue: bias + activation + store (float2 per pair)
#pragma unroll
    for (int mt = 0; mt < 4; mt++) {
#pragma unroll
        for (int nt = 0; nt < 4; nt++) {
            const size_t row = blockM + wm + mt * 16 + g;
            const size_t col = blockN + wn + nt * 8 + 2 * tig;
            const float bv0 = bias[col];
            const float bv1 = bias[col + 1];
            float2 v0, v1;
            v0.x = epi_act<EPI>(c[mt][nt][0] + bv0);
            v0.y = epi_act<EPI>(c[mt][nt][1] + bv1);
            v1.x = epi_act<EPI>(c[mt][nt][2] + bv0);
            v1.y = epi_act<EPI>(c[mt][nt][3] + bv1);
            *reinterpret_cast<float2*>(&C[row * N + col])       = v0;
            *reinterpret_cast<float2*>(&C[(row + 8) * N + col]) = v1;
        }
    }
}

// ---------------------------------------------------------------------------
// Recurrence: buf_t = buf_{t-1} * d_t + (1-d_t) * x_t  (linear recurrence)
// Chunked scan over S: pass1 computes per-chunk (P = prod d, Q = local sol),
// pass2 folds chunk summaries for the initial buf and emits
// combined = x*d + buf.
// ---------------------------------------------------------------------------
__global__ void recur_pass1(const float* __restrict__ x) {
    const int idx   = blockIdx.x * blockDim.x + threadIdx.x;  // 0..NCHUNK*NCH-1
    const int ch    = idx & (NCH - 1);
    const int chunk = idx >> 13;           // / NCH
    const int b     = ch >> 10;            // / Id
    const int i     = ch & (Id - 1);
    size_t base = (size_t)b * Sd * Id + (size_t)chunk * CHUNK * Id + i;

    float P = 1.f, Q = 0.f;
#pragma unroll 8
    for (int t = 0; t < CHUNK; t++) {
        const float d  = g_decay[base + (size_t)t * Id];
        const float xv = x[base + (size_t)t * Id];
        P *= d;
        Q = Q * d + (1.f - d) * xv;
    }
    g_P[chunk * NCH + ch] = P;
    g_Q[chunk * NCH + ch] = Q;
}

__global__ void recur_pass2(const float* __restrict__ x) {
    const int idx   = blockIdx.x * blockDim.x + threadIdx.x;
    const int ch    = idx & (NCH - 1);
    const int chunk = idx >> 13;
    const int b     = ch >> 10;
    const int i     = ch & (Id - 1);
    size_t base = (size_t)b * Sd * Id + (size_t)chunk * CHUNK * Id + i;

    // fold prior chunk summaries to get the initial buffer for this chunk
    float buf = 0.f;
    for (int j = 0; j < chunk; j++)
        buf = g_P[j * NCH + ch] * buf + g_Q[j * NCH + ch];

#pragma unroll 8
    for (int t = 0; t < CHUNK; t++) {
        const float d  = g_decay[base + (size_t)t * Id];
        const float xv = x[base + (size_t)t * Id];
        buf = buf * d + (1.f - d) * xv;
        g_combined[base + (size_t)t * Id] = xv * d + buf;
    }
}

// ---------------------------------------------------------------------------
// Launch
// ---------------------------------------------------------------------------
extern "C" void kernel_launch(void* const* d_in, const int* in_sizes, int n_in,
                              void* d_out, int out_size) {
    const float* x  = (const float*)d_in[0];
    const float* W1 = (const float*)d_in[1];
    const float* b1 = (const float*)d_in[2];
    const float* W2 = (const float*)d_in[3];
    const float* b2 = (const float*)d_in[4];
    const float* Wg = (const float*)d_in[5];
    const float* bg = (const float*)d_in[6];
    float* out = (float*)d_out;

    float *decay, *combined, *hidden;
    cudaGetSymbolAddress((void**)&decay, g_decay);
    cudaGetSymbolAddress((void**)&combined, g_combined);
    cudaGetSymbolAddress((void**)&hidden, g_hidden);

    // 1) decay = sigmoid(x @ Wg^T + bg)
    gemm_tn<2><<<dim3(Id / 128, M_TOT / 128), 256>>>(x, Wg, bg, decay,
                                                     M_TOT, Id, Id);
    // 2) chunked linear-recurrence scan -> combined
    recur_pass1<<<(NCHUNK * NCH) / 256, 256>>>(x);
    recur_pass2<<<(NCHUNK * NCH) / 256, 256>>>(x);
    // 3) hidden = relu(combined @ W1^T + b1)
    gemm_tn<1><<<dim3(Hd / 128, M_TOT / 128), 256>>>(combined, W1, b1, hidden,
                                                     M_TOT, Hd, Id);
    // 4) out = hidden @ W2^T + b2
    gemm_tn<0><<<dim3(Od / 128, M_TOT / 128), 256>>>(hidden, W2, b2, out,
                                                     M_TOT, Od, Hd);
}

// round 4
// speedup vs baseline: 1.0071x; 1.0071x over previous
#include <cuda_runtime.h>
#include <cstdint>

// ---------------------------------------------------------------------------
// Problem dims (fixed)
// ---------------------------------------------------------------------------
#define Bd 8
#define Sd 2048
#define Id 1024
#define Hd 4096
#define Od 1024
#define M_TOT (Bd * Sd)          // 16384

#define NCHUNK 16
#define CHUNK  128
#define NCH    (Bd * Id)         // 8192

// ---------------------------------------------------------------------------
// Scratch (__device__ globals, allocation-free)
// ---------------------------------------------------------------------------
__device__ float g_decay[(size_t)M_TOT * Id];     // 64 MB
__device__ float g_combined[(size_t)M_TOT * Id];  // 64 MB (tf32-rounded)
__device__ float g_hidden[(size_t)M_TOT * Hd];    // 256 MB (tf32-rounded)
__device__ float g_P[NCHUNK * NCH];
__device__ float g_Q[NCHUNK * NCH];

// ---------------------------------------------------------------------------
// Helpers
// ---------------------------------------------------------------------------
__device__ __forceinline__ uint32_t f2tf(float x) {
    uint32_t u;
    asm("cvt.rna.tf32.f32 %0, %1;" : "=r"(u) : "f"(x));
    return u;
}

__device__ __forceinline__ uint4 cvt4(float4 v) {
    uint4 u;
    u.x = f2tf(v.x); u.y = f2tf(v.y); u.z = f2tf(v.z); u.w = f2tf(v.w);
    return u;
}

__device__ __forceinline__ void mma8(float c[4], const uint32_t a[4], const uint32_t b[2]) {
    asm volatile(
        "mma.sync.aligned.m16n8k8.row.col.f32.tf32.tf32.f32 "
        "{%0,%1,%2,%3}, {%4,%5,%6,%7}, {%8,%9}, {%0,%1,%2,%3};"
        : "+f"(c[0]), "+f"(c[1]), "+f"(c[2]), "+f"(c[3])
        : "r"(a[0]), "r"(a[1]), "r"(a[2]), "r"(a[3]), "r"(b[0]), "r"(b[1]));
}

template <int EPI>
__device__ __forceinline__ float epi_act(float v) {
    if (EPI == 1) {                                 // relu + tf32 round
        v = v > 0.f ? v : 0.f;
        return __uint_as_float(f2tf(v));
    }
    if (EPI == 2) return 1.f / (1.f + __expf(-v));  // sigmoid
    return v;
}

// ---------------------------------------------------------------------------
// TF32 GEMM, fragment-ordered smem layout.
// C[M,N] = act(A[M,K] @ B[N,K]^T + bias[N])
// CTA tile 128x128, 4 warps (2x2 grid of 64x64 warp tiles), K slab = 16,
// double-buffered. Producers (all threads) do LDG.128 -> tf32 -> scattered
// STS.32 into fragment order; consumers load A-frags with LDS.128 and
// B-frags with LDS.64, conflict-free.
//
// A region: 16 frag-blocks (mt_g 0..7  x kk 0..1), block = 528 B (512+16 pad)
// B region: 32 frag-blocks (nt_g 0..15 x kk 0..1), block = 264 B (256+8 pad)
// Within a block, lane unit u = g*4 + (tig ^ (g&3)); A word at u*16+slot*4
// (slot = half + 2*chalf), B word at u*8 + chalf*4.
// ---------------------------------------------------------------------------
#define ABLK 528
#define BBLK 264
#define AREG (16 * ABLK)               // 8448
#define STAGE (AREG + 32 * BBLK)       // 16896

__device__ __forceinline__ void sts_a(char* bufA, int row, int kk, int chalf,
                                      int j, uint32_t w) {
    const int mt = row >> 4, lr = row & 15, gg = lr & 7, half = lr >> 3;
    const int u = gg * 4 + (j ^ (gg & 3));
    *reinterpret_cast<uint32_t*>(bufA + (mt * 2 + kk) * ABLK + u * 16 +
                                 (half + 2 * chalf) * 4) = w;
}

__device__ __forceinline__ void sts_b(char* bufB, int col, int kk, int chalf,
                                      int j, uint32_t w) {
    const int nt = col >> 3, gg = col & 7;
    const int u = gg * 4 + (j ^ (gg & 3));
    *reinterpret_cast<uint32_t*>(bufB + (nt * 2 + kk) * BBLK + u * 8 +
                                 chalf * 4) = w;
}

template <int EPI>  // 0=none, 1=relu+round, 2=sigmoid
__global__ void __launch_bounds__(128, 2)
gemm_tn(const float* __restrict__ A, const float* __restrict__ Bm,
        const float* __restrict__ bias, float* __restrict__ C,
        int M, int N, int K) {
    __shared__ __align__(16) char sm[2][STAGE];

    const int tid  = threadIdx.x;
    const int lane = tid & 31;
    const int warp = tid >> 5;
    const int g    = lane >> 2;
    const int tig  = lane & 3;
    const int wm   = (warp >> 1) * 64;   // warp M offset
    const int wn   = (warp & 1) * 64;    // warp N offset
    const int uA   = g * 4 + (tig ^ (g & 3));  // consumer unit index

    // producer coords
    const int prow  = tid >> 2;          // 0..31 (base row/col, +q*32)
    const int pc    = (tid & 3) * 4;     // k offset within slab: 0,4,8,12
    const int kk_p  = pc >> 3;
    const int ch_p  = (pc >> 2) & 1;

    const size_t blockM = (size_t)blockIdx.y * 128;
    const size_t blockN = (size_t)blockIdx.x * 128;

    const float* Ab = A  + (blockM + prow) * (size_t)K + pc;
    const float* Bb = Bm + (blockN + prow) * (size_t)K + pc;

    float c[4][8][4] = {};
    float4 pa[4], pb[4];

    // ---- prologue: slab 0 ----
#pragma unroll
    for (int q = 0; q < 4; q++) {
        pa[q] = *reinterpret_cast<const float4*>(Ab + (size_t)(q * 32) * K);
        pb[q] = *reinterpret_cast<const float4*>(Bb + (size_t)(q * 32) * K);
    }
#pragma unroll
    for (int q = 0; q < 4; q++) {
        uint4 wa = cvt4(pa[q]);
        uint4 wb = cvt4(pb[q]);
        const int rc = prow + q * 32;
        sts_a(sm[0], rc, kk_p, ch_p, 0, wa.x);
        sts_a(sm[0], rc, kk_p, ch_p, 1, wa.y);
        sts_a(sm[0], rc, kk_p, ch_p, 2, wa.z);
        sts_a(sm[0], rc, kk_p, ch_p, 3, wa.w);
        sts_b(sm[0] + AREG, rc, kk_p, ch_p, 0, wb.x);
        sts_b(sm[0] + AREG, rc, kk_p, ch_p, 1, wb.y);
        sts_b(sm[0] + AREG, rc, kk_p, ch_p, 2, wb.z);
        sts_b(sm[0] + AREG, rc, kk_p, ch_p, 3, wb.w);
    }
    __syncthreads();

    const int nk = K >> 4;
    for (int kt = 0; kt < nk; kt++) {
        const int buf = kt & 1;
        const bool has_next = (kt + 1 < nk);
        if (has_next) {
            const int k0 = (kt + 1) << 4;
#pragma unroll
            for (int q = 0; q < 4; q++) {
                pa[q] = *reinterpret_cast<const float4*>(Ab + (size_t)(q * 32) * K + k0);
                pb[q] = *reinterpret_cast<const float4*>(Bb + (size_t)(q * 32) * K + k0);
            }
        }

        // ---- compute on sm[buf] ----
        const char* bufA = sm[buf];
        const char* bufB = sm[buf] + AREG;
#pragma unroll
        for (int kk = 0; kk < 2; kk++) {
            uint32_t af[4][4];
            uint32_t bf[8][2];
#pragma unroll
            for (int mt = 0; mt < 4; mt++) {
                uint4 v = *reinterpret_cast<const uint4*>(
                    bufA + (((wm >> 4) + mt) * 2 + kk) * ABLK + uA * 16);
                af[mt][0] = v.x; af[mt][1] = v.y; af[mt][2] = v.z; af[mt][3] = v.w;
            }
#pragma unroll
            for (int nt = 0; nt < 8; nt++) {
                uint2 v = *reinterpret_cast<const uint2*>(
                    bufB + (((wn >> 3) + nt) * 2 + kk) * BBLK + uA * 8);
                bf[nt][0] = v.x; bf[nt][1] = v.y;
            }
#pragma unroll
            for (int mt = 0; mt < 4; mt++)
#pragma unroll
                for (int nt = 0; nt < 8; nt++)
                    mma8(c[mt][nt], af[mt], bf[nt]);
        }

        if (has_next) {
            char* nA = sm[buf ^ 1];
            char* nB = sm[buf ^ 1] + AREG;
#pragma unroll
            for (int q = 0; q < 4; q++) {
                uint4 wa = cvt4(pa[q]);
                uint4 wb = cvt4(pb[q]);
                const int rc = prow + q * 32;
                sts_a(nA, rc, kk_p, ch_p, 0, wa.x);
                sts_a(nA, rc, kk_p, ch_p, 1, wa.y);
                sts_a(nA, rc, kk_p, ch_p, 2, wa.z);
                sts_a(nA, rc, kk_p, ch_p, 3, wa.w);
                sts_b(nB, rc, kk_p, ch_p, 0, wb.x);
                sts_b(nB, rc, kk_p, ch_p, 1, wb.y);
                sts_b(nB, rc, kk_p, ch_p, 2, wb.z);
                sts_b(nB, rc, kk_p, ch_p, 3, wb.w);
            }
        }
        __syncthreads();
    }

    // ---- epilogue: bias + activation + store ----
#pragma unroll
    for (int mt = 0; mt < 4; mt++) {
#pragma unroll
        for (int nt = 0; nt < 8; nt++) {
            const size_t row = blockM + wm + mt * 16 + g;
            const size_t col = blockN + wn + nt * 8 + 2 * tig;
            const float bv0 = bias[col];
            const float bv1 = bias[col + 1];
            float2 v0, v1;
            v0.x = epi_act<EPI>(c[mt][nt][0] + bv0);
            v0.y = epi_act<EPI>(c[mt][nt][1] + bv1);
            v1.x = epi_act<EPI>(c[mt][nt][2] + bv0);
            v1.y = epi_act<EPI>(c[mt][nt][3] + bv1);
            *reinterpret_cast<float2*>(&C[row * N + col])       = v0;
            *reinterpret_cast<float2*>(&C[(row + 8) * N + col]) = v1;
        }
    }
}

// ---------------------------------------------------------------------------
// Recurrence (chunked linear scan), pass2 writes tf32-rounded combined
// ---------------------------------------------------------------------------
__global__ void recur_pass1(const float* __restrict__ x) {
    const int idx   = blockIdx.x * blockDim.x + threadIdx.x;
    const int ch    = idx & (NCH - 1);
    const int chunk = idx >> 13;
    const int b     = ch >> 10;
    const int i     = ch & (Id - 1);
    size_t base = (size_t)b * Sd * Id + (size_t)chunk * CHUNK * Id + i;

    float P = 1.f, Q = 0.f;
#pragma unroll 8
    for (int t = 0; t < CHUNK; t++) {
        const float d  = g_decay[base + (size_t)t * Id];
        const float xv = x[base + (size_t)t * Id];
        P *= d;
        Q = Q * d + (1.f - d) * xv;
    }
    g_P[chunk * NCH + ch] = P;
    g_Q[chunk * NCH + ch] = Q;
}

__global__ void recur_pass2(const float* __restrict__ x) {
    const int idx   = blockIdx.x * blockDim.x + threadIdx.x;
    const int ch    = idx & (NCH - 1);
    const int chunk = idx >> 13;
    const int b     = ch >> 10;
    const int i     = ch & (Id - 1);
    size_t base = (size_t)b * Sd * Id + (size_t)chunk * CHUNK * Id + i;

    float buf = 0.f;
    for (int j = 0; j < chunk; j++)
        buf = g_P[j * NCH + ch] * buf + g_Q[j * NCH + ch];

#pragma unroll 8
    for (int t = 0; t < CHUNK; t++) {
        const float d  = g_decay[base + (size_t)t * Id];
        const float xv = x[base + (size_t)t * Id];
        buf = buf * d + (1.f - d) * xv;
        g_combined[base + (size_t)t * Id] = __uint_as_float(f2tf(xv * d + buf));
    }
}

// ---------------------------------------------------------------------------
// Launch
// ---------------------------------------------------------------------------
extern "C" void kernel_launch(void* const* d_in, const int* in_sizes, int n_in,
                              void* d_out, int out_size) {
    const float* x  = (const float*)d_in[0];
    const float* W1 = (const float*)d_in[1];
    const float* b1 = (const float*)d_in[2];
    const float* W2 = (const float*)d_in[3];
    const float* b2 = (const float*)d_in[4];
    const float* Wg = (const float*)d_in[5];
    const float* bg = (const float*)d_in[6];
    float* out = (float*)d_out;

    float *decay, *combined, *hidden;
    cudaGetSymbolAddress((void**)&decay, g_decay);
    cudaGetSymbolAddress((void**)&combined, g_combined);
    cudaGetSymbolAddress((void**)&hidden, g_hidden);

    // 1) decay = sigmoid(x @ Wg^T + bg)
    gemm_tn<2><<<dim3(Id / 128, M_TOT / 128), 128>>>(x, Wg, bg, decay,
                                                     M_TOT, Id, Id);
    // 2) chunked linear-recurrence scan -> combined (tf32-rounded)
    recur_pass1<<<(NCHUNK * NCH) / 256, 256>>>(x);
    recur_pass2<<<(NCHUNK * NCH) / 256, 256>>>(x);
    // 3) hidden = relu(combined @ W1^T + b1), tf32-rounded
    gemm_tn<1><<<dim3(Hd / 128, M_TOT / 128), 128>>>(combined, W1, b1, hidden,
                                                     M_TOT, Hd, Id);
    // 4) out = hidden @ W2^T + b2
    gemm_tn<0><<<dim3(Od / 128, M_TOT / 128), 128>>>(hidden, W2, b2, out,
                                                     M_TOT, Od, Hd);
}

// round 5
// speedup vs baseline: 2.9311x; 2.9104x over previous
#include <cuda_runtime.h>
#include <cuda_fp16.h>
#include <cstdint>

// ---------------------------------------------------------------------------
// Problem dims (fixed)
// ---------------------------------------------------------------------------
#define Bd 8
#define Sd 2048
#define Id 1024
#define Hd 4096
#define Od 1024
#define M_TOT (Bd * Sd)          // 16384

#define NCHUNK 16
#define CHUNK  128
#define NCH    (Bd * Id)         // 8192

// ---------------------------------------------------------------------------
// Scratch (__device__ globals, allocation-free)
// ---------------------------------------------------------------------------
__device__ __half g_xh[(size_t)M_TOT * Id];        // 32 MB
__device__ __half g_Wgh[(size_t)Id * Id];          //  2 MB
__device__ __half g_W1h[(size_t)Hd * Id];          //  8 MB
__device__ __half g_W2h[(size_t)Od * Hd];          //  8 MB
__device__ float  g_decay[(size_t)M_TOT * Id];     // 64 MB
__device__ __half g_comb[(size_t)M_TOT * Id];      // 32 MB
__device__ __half g_hidden[(size_t)M_TOT * Hd];    // 128 MB
__device__ float  g_P[NCHUNK * NCH];
__device__ float  g_Q[NCHUNK * NCH];

// ---------------------------------------------------------------------------
// PTX helpers
// ---------------------------------------------------------------------------
__device__ __forceinline__ uint32_t smem_u32(const void* p) {
    uint32_t a;
    asm("{ .reg .u64 t; cvta.to.shared.u64 t, %1; cvt.u32.u64 %0, t; }"
        : "=r"(a) : "l"(p));
    return a;
}

#define CP_ASYNC16(dst, src) \
    asm volatile("cp.async.cg.shared.global [%0], [%1], 16;" :: "r"(dst), "l"(src))
#define CP_COMMIT() asm volatile("cp.async.commit_group;" ::: "memory")
#define CP_WAIT(n)  asm volatile("cp.async.wait_group %0;" :: "n"(n) : "memory")

#define LDSM_X4(r0, r1, r2, r3, addr)                                        \
    asm volatile("ldmatrix.sync.aligned.m8n8.x4.shared.b16 {%0,%1,%2,%3}, [%4];" \
        : "=r"(r0), "=r"(r1), "=r"(r2), "=r"(r3) : "r"(addr))

__device__ __forceinline__ void mma16(float c[4], const uint32_t a[4], const uint32_t b[2]) {
    asm volatile(
        "mma.sync.aligned.m16n8k16.row.col.f32.f16.f16.f32 "
        "{%0,%1,%2,%3}, {%4,%5,%6,%7}, {%8,%9}, {%0,%1,%2,%3};"
        : "+f"(c[0]), "+f"(c[1]), "+f"(c[2]), "+f"(c[3])
        : "r"(a[0]), "r"(a[1]), "r"(a[2]), "r"(a[3]), "r"(b[0]), "r"(b[1]));
}

// ---------------------------------------------------------------------------
// fp16 GEMM: C[M,N] = act(A[M,K] @ B[N,K]^T + bias[N]); A,B fp16 K-contig.
// CTA tile 128x128, 4 warps (2x2 of 64x64 warp tiles), K-slab 64
// (128B fp16 rows), double-buffered cp.async pipeline, XOR-16B swizzle,
// ldmatrix.x4 fragment loads, fp32 accumulate.
// EPI: 0 = none (f32 out), 1 = relu (f16 out), 2 = sigmoid (f32 out)
// ---------------------------------------------------------------------------
#define KSLAB 64
#define ATILE 16384                   // 128 rows * 128 B
#define STAGE (2 * ATILE)             // A + B = 32 KB
#define DYN_SMEM (2 * STAGE)          // 64 KB

__device__ __forceinline__ void fill_slab(uint32_t sbuf, const __half* ga,
                                          const __half* gb, int K, int k0, int tid) {
    const int r0 = tid >> 3;          // 0..15
    const int c  = tid & 7;           // 16B chunk within 128B row
#pragma unroll
    for (int q = 0; q < 8; q++) {
        const int row = r0 + q * 16;
        const uint32_t sw = (uint32_t)((c ^ (row & 7)) << 4);
        CP_ASYNC16(sbuf + row * 128 + sw, ga + (size_t)row * K + k0 + c * 8);
    }
#pragma unroll
    for (int q = 0; q < 8; q++) {
        const int row = r0 + q * 16;
        const uint32_t sw = (uint32_t)((c ^ (row & 7)) << 4);
        CP_ASYNC16(sbuf + ATILE + row * 128 + sw, gb + (size_t)row * K + k0 + c * 8);
    }
}

template <int EPI>
__global__ void __launch_bounds__(128, 2)
gemm_h(const __half* __restrict__ A, const __half* __restrict__ Bm,
       const float* __restrict__ bias, void* __restrict__ Cout,
       int M, int N, int K) {
    extern __shared__ char smem[];
    const uint32_t sb = smem_u32(smem);

    const int tid  = threadIdx.x;
    const int lane = tid & 31;
    const int warp = tid >> 5;
    const int g    = lane >> 2;
    const int tig  = lane & 3;
    const int wm   = (warp >> 1) * 64;
    const int wn   = (warp & 1) * 64;

    // ldmatrix lane->address mapping (see theory): A covers m16 x k16 tiles,
    // B covers n16 x k16 tiles (two mma B-frags per LDSM.x4).
    const int rA = wm + (lane & 15);
    const int cA = lane >> 4;                       // 0/1 -> k-half
    const int xA = rA & 7;
    const int rB = wn + (lane & 7) + ((lane >> 4) << 3);
    const int cB = (lane >> 3) & 1;
    const int xB = rB & 7;

    const size_t blockM = (size_t)blockIdx.y * 128;
    const size_t blockN = (size_t)blockIdx.x * 128;
    const __half* ga = A  + blockM * (size_t)K;
    const __half* gb = Bm + blockN * (size_t)K;

    float c[4][8][4] = {};

    const int nk = K / KSLAB;
    fill_slab(sb,         ga, gb, K, 0,     tid); CP_COMMIT();
    fill_slab(sb + STAGE, ga, gb, K, KSLAB, tid); CP_COMMIT();

    for (int kt = 0; kt < nk; kt++) {
        if (kt < nk - 1) { CP_WAIT(1); } else { CP_WAIT(0); }
        __syncthreads();

        const uint32_t buf = sb + (kt & 1) * STAGE;
#pragma unroll
        for (int kk = 0; kk < 4; kk++) {            // 4 x k16 per slab
            uint32_t af[4][4], bf[8][2];
#pragma unroll
            for (int mt = 0; mt < 4; mt++) {
                const uint32_t addr = buf + (rA + mt * 16) * 128 +
                                      (uint32_t)(((kk * 2 + cA) ^ xA) << 4);
                LDSM_X4(af[mt][0], af[mt][1], af[mt][2], af[mt][3], addr);
            }
#pragma unroll
            for (int p = 0; p < 4; p++) {
                const uint32_t addr = buf + ATILE + (rB + p * 16) * 128 +
                                      (uint32_t)(((kk * 2 + cB) ^ xB) << 4);
                LDSM_X4(bf[2 * p][0], bf[2 * p][1], bf[2 * p + 1][0], bf[2 * p + 1][1], addr);
            }
#pragma unroll
            for (int mt = 0; mt < 4; mt++)
#pragma unroll
                for (int nt = 0; nt < 8; nt++)
                    mma16(c[mt][nt], af[mt], bf[nt]);
        }
        __syncthreads();

        if (kt + 2 < nk) {
            fill_slab(sb + (kt & 1) * STAGE, ga, gb, K, (kt + 2) * KSLAB, tid);
            CP_COMMIT();
        } else {
            CP_COMMIT();   // keep group count in lockstep with wait schedule
        }
    }

    // ---- epilogue ----
#pragma unroll
    for (int mt = 0; mt < 4; mt++) {
#pragma unroll
        for (int nt = 0; nt < 8; nt++) {
            const size_t row = blockM + wm + mt * 16 + g;
            const size_t col = blockN + wn + nt * 8 + 2 * tig;
            const float bv0 = __ldg(bias + col);
            const float bv1 = __ldg(bias + col + 1);
            float v00 = c[mt][nt][0] + bv0, v01 = c[mt][nt][1] + bv1;
            float v10 = c[mt][nt][2] + bv0, v11 = c[mt][nt][3] + bv1;
            if (EPI == 1) {
                v00 = v00 > 0.f ? v00 : 0.f;  v01 = v01 > 0.f ? v01 : 0.f;
                v10 = v10 > 0.f ? v10 : 0.f;  v11 = v11 > 0.f ? v11 : 0.f;
                __half* Ch = (__half*)Cout;
                *reinterpret_cast<__half2*>(&Ch[row * N + col]) =
                    __floats2half2_rn(v00, v01);
                *reinterpret_cast<__half2*>(&Ch[(row + 8) * N + col]) =
                    __floats2half2_rn(v10, v11);
            } else {
                if (EPI == 2) {
                    v00 = 1.f / (1.f + __expf(-v00)); v01 = 1.f / (1.f + __expf(-v01));
                    v10 = 1.f / (1.f + __expf(-v10)); v11 = 1.f / (1.f + __expf(-v11));
                }
                float* Cf = (float*)Cout;
                *reinterpret_cast<float2*>(&Cf[row * N + col]) = make_float2(v00, v01);
                *reinterpret_cast<float2*>(&Cf[(row + 8) * N + col]) = make_float2(v10, v11);
            }
        }
    }
}

// ---------------------------------------------------------------------------
// fp32 -> fp16 conversion (vectorized)
// ---------------------------------------------------------------------------
__global__ void f2h(const float* __restrict__ src, __half* __restrict__ dst, int n4) {
    const int i = blockIdx.x * blockDim.x + threadIdx.x;
    if (i < n4) {
        float4 v = reinterpret_cast<const float4*>(src)[i];
        __half2 h0 = __floats2half2_rn(v.x, v.y);
        __half2 h1 = __floats2half2_rn(v.z, v.w);
        uint2 u;
        u.x = *reinterpret_cast<uint32_t*>(&h0);
        u.y = *reinterpret_cast<uint32_t*>(&h1);
        reinterpret_cast<uint2*>(dst)[i] = u;
    }
}

// ---------------------------------------------------------------------------
// Recurrence (chunked linear scan); pass2 emits fp16 combined
// ---------------------------------------------------------------------------
__global__ void recur_pass1(const float* __restrict__ x) {
    const int idx   = blockIdx.x * blockDim.x + threadIdx.x;
    const int ch    = idx & (NCH - 1);
    const int chunk = idx >> 13;
    const int b     = ch >> 10;
    const int i     = ch & (Id - 1);
    size_t base = (size_t)b * Sd * Id + (size_t)chunk * CHUNK * Id + i;

    float P = 1.f, Q = 0.f;
#pragma unroll 8
    for (int t = 0; t < CHUNK; t++) {
        const float d  = g_decay[base + (size_t)t * Id];
        const float xv = x[base + (size_t)t * Id];
        P *= d;
        Q = Q * d + (1.f - d) * xv;
    }
    g_P[chunk * NCH + ch] = P;
    g_Q[chunk * NCH + ch] = Q;
}

__global__ void recur_pass2(const float* __restrict__ x) {
    const int idx   = blockIdx.x * blockDim.x + threadIdx.x;
    const int ch    = idx & (NCH - 1);
    const int chunk = idx >> 13;
    const int b     = ch >> 10;
    const int i     = ch & (Id - 1);
    size_t base = (size_t)b * Sd * Id + (size_t)chunk * CHUNK * Id + i;

    float buf = 0.f;
    for (int j = 0; j < chunk; j++)
        buf = g_P[j * NCH + ch] * buf + g_Q[j * NCH + ch];

#pragma unroll 8
    for (int t = 0; t < CHUNK; t++) {
        const float d  = g_decay[base + (size_t)t * Id];
        const float xv = x[base + (size_t)t * Id];
        buf = buf * d + (1.f - d) * xv;
        g_comb[base + (size_t)t * Id] = __float2half_rn(xv * d + buf);
    }
}

// ---------------------------------------------------------------------------
// Launch
// ---------------------------------------------------------------------------
extern "C" void kernel_launch(void* const* d_in, const int* in_sizes, int n_in,
                              void* d_out, int out_size) {
    const float* x  = (const float*)d_in[0];
    const float* W1 = (const float*)d_in[1];
    const float* b1 = (const float*)d_in[2];
    const float* W2 = (const float*)d_in[3];
    const float* b2 = (const float*)d_in[4];
    const float* Wg = (const float*)d_in[5];
    const float* bg = (const float*)d_in[6];

    __half *xh, *Wgh, *W1h, *W2h, *comb, *hidden;
    float *decay;
    cudaGetSymbolAddress((void**)&xh, g_xh);
    cudaGetSymbolAddress((void**)&Wgh, g_Wgh);
    cudaGetSymbolAddress((void**)&W1h, g_W1h);
    cudaGetSymbolAddress((void**)&W2h, g_W2h);
    cudaGetSymbolAddress((void**)&decay, g_decay);
    cudaGetSymbolAddress((void**)&comb, g_comb);
    cudaGetSymbolAddress((void**)&hidden, g_hidden);

    cudaFuncSetAttribute(gemm_h<0>, cudaFuncAttributeMaxDynamicSharedMemorySize, DYN_SMEM);
    cudaFuncSetAttribute(gemm_h<1>, cudaFuncAttributeMaxDynamicSharedMemorySize, DYN_SMEM);
    cudaFuncSetAttribute(gemm_h<2>, cudaFuncAttributeMaxDynamicSharedMemorySize, DYN_SMEM);

    // 0) fp16 copies of MMA operand inputs
    f2h<<<(M_TOT * Id / 4) / 256, 256>>>(x, xh, M_TOT * Id / 4);
    f2h<<<(Id * Id / 4) / 256, 256>>>(Wg, Wgh, Id * Id / 4);
    f2h<<<(Hd * Id / 4) / 256, 256>>>(W1, W1h, Hd * Id / 4);
    f2h<<<(Od * Hd / 4) / 256, 256>>>(W2, W2h, Od * Hd / 4);

    // 1) decay = sigmoid(x @ Wg^T + bg)
    gemm_h<2><<<dim3(Id / 128, M_TOT / 128), 128, DYN_SMEM>>>(
        xh, Wgh, bg, decay, M_TOT, Id, Id);
    // 2) recurrence -> combined (fp16)
    recur_pass1<<<(NCHUNK * NCH) / 256, 256>>>(x);
    recur_pass2<<<(NCHUNK * NCH) / 256, 256>>>(x);
    // 3) hidden = relu(combined @ W1^T + b1) -> fp16
    gemm_h<1><<<dim3(Hd / 128, M_TOT / 128), 128, DYN_SMEM>>>(
        comb, W1h, b1, hidden, M_TOT, Hd, Id);
    // 4) out = hidden @ W2^T + b2 -> fp32
    gemm_h<0><<<dim3(Od / 128, M_TOT / 128), 128, DYN_SMEM>>>(
        hidden, W2h, b2, d_out, M_TOT, Od, Hd);
}